// round 3
// baseline (speedup 1.0000x reference)
#include <cuda_runtime.h>
#include <cstdint>
#include <cstddef>

// ---------------------------------------------------------------------------
// BaseGIN: 3-layer GIN on a 100k-node / 1.6M-edge graph.
//
// Per layer (reformulated; aggregation is linear so project-then-aggregate):
//   y = A_in @ Wa                      (GEMM-A, K=128 for layer 1 else 64)
//   z = (1+eps)*y + ba                 (fused into GEMM-A epilogue)
//   z[dst] += w_e * y[src]             (edge scatter, red.global.add.v4.f32)
//   u = relu(z) @ Wb + bb              (GEMM-B, relu fused on A-load)
//   stats: per-column sum / sumsq of u (fused into GEMM-B epilogue)
//   h' = relu((u-mean)*rsqrt(var+eps)*gamma + beta)  [+ h  for layers 2,3]
// ---------------------------------------------------------------------------

static constexpr int H   = 64;
static constexpr int BM  = 128;   // rows per GEMM block
static constexpr int KC  = 16;    // k-chunk
static constexpr int MAXN = 131072;

__device__ __align__(16) float g_y[MAXN * H];
__device__ __align__(16) float g_z[MAXN * H];
__device__ __align__(16) float g_u[MAXN * H];
__device__ __align__(16) float g_h[MAXN * H];
__device__ float g_stats[2 * H];
__device__ int   g_idx64;   // 1 if edge_index buffer is int64, 0 if int32

// ---- packed f32x2 helpers (Blackwell FFMA2 is only reachable via PTX) -----
__device__ __forceinline__ unsigned long long pk2(float a, float b) {
    unsigned long long r;
    asm("mov.b64 %0, {%1,%2};" : "=l"(r) : "f"(a), "f"(b));
    return r;
}
__device__ __forceinline__ void fma2(unsigned long long& d,
                                     unsigned long long a, unsigned long long b) {
    asm("fma.rn.f32x2 %0, %1, %2, %0;" : "+l"(d) : "l"(a), "l"(b));
}
__device__ __forceinline__ float2 up2(unsigned long long v) {
    float lo, hi;
    asm("mov.b64 {%0,%1}, %2;" : "=f"(lo), "=f"(hi) : "l"(v));
    return make_float2(lo, hi);
}

// ---------------------------------------------------------------------------
// Detect edge_index dtype. If it is int64 with values < 2^31, every odd
// 32-bit word of the first 64 entries is zero. If int32, those words are
// random node indices (prob of all-zero ~ 1e-320).
// ---------------------------------------------------------------------------
__global__ void detect_k(const unsigned* __restrict__ ei32) {
    int is64 = 1;
#pragma unroll
    for (int i = 0; i < 64; i++)
        if (ei32[2 * i + 1] != 0u) is64 = 0;
    g_idx64 = is64;
}

// ---------------------------------------------------------------------------
// GEMM-A: y = A @ W ;  z = (1+eps)*y + ba
// A is the external input x (K=128) or g_h (K=64).
// Block: 128 rows x 64 cols, 256 threads, thread = 8 rows x 4 cols
// (4 row-pairs x 4 cols of f32x2 accumulators).
// ---------------------------------------------------------------------------
template <int K>
__global__ __launch_bounds__(256) void gemm_a(
    const float* __restrict__ Ain, const float* __restrict__ W,
    const float* __restrict__ ba, const float* __restrict__ eps_p, int N)
{
    const float* A = (K == 128) ? Ain : (const float*)g_h;
    __shared__ float Ws[K][H];
    __shared__ float As[KC][BM];

    const int tid = threadIdx.x;
    const int tx = tid & 15;   // col group: cols tx*4 .. tx*4+3
    const int ty = tid >> 4;   // row group: rows ty*8 .. ty*8+7
    const int bm0 = blockIdx.x * BM;

    // stage full W (K x 64) into smem
    for (int i = tid * 4; i < K * H; i += 1024)
        *(float4*)((float*)Ws + i) = *(const float4*)&W[i];

    unsigned long long acc[4][4];
#pragma unroll
    for (int i = 0; i < 4; i++)
#pragma unroll
        for (int j = 0; j < 4; j++) acc[i][j] = 0ULL;

    for (int kb = 0; kb < K; kb += KC) {
        __syncthreads();
#pragma unroll
        for (int it = 0; it < 2; it++) {
            int e  = it * 256 + tid;      // 0..511
            int rl = e >> 2;              // local row 0..127
            int kq = (e & 3) * 4;         // k offset 0,4,8,12
            int r  = bm0 + rl;
            float4 v = make_float4(0.f, 0.f, 0.f, 0.f);
            if (r < N) v = *(const float4*)&A[(size_t)r * K + kb + kq];
            As[kq + 0][rl] = v.x; As[kq + 1][rl] = v.y;
            As[kq + 2][rl] = v.z; As[kq + 3][rl] = v.w;
        }
        __syncthreads();
#pragma unroll
        for (int k = 0; k < KC; k++) {
            float4 a0 = *(float4*)&As[k][ty * 8];
            float4 a1 = *(float4*)&As[k][ty * 8 + 4];
            float4 w  = *(float4*)&Ws[kb + k][tx * 4];
            unsigned long long ap[4] = { pk2(a0.x, a0.y), pk2(a0.z, a0.w),
                                         pk2(a1.x, a1.y), pk2(a1.z, a1.w) };
            unsigned long long wd[4] = { pk2(w.x, w.x), pk2(w.y, w.y),
                                         pk2(w.z, w.z), pk2(w.w, w.w) };
#pragma unroll
            for (int rp = 0; rp < 4; rp++)
#pragma unroll
                for (int c = 0; c < 4; c++) fma2(acc[rp][c], ap[rp], wd[c]);
        }
    }

    const float ep1 = 1.0f + *eps_p;
    const float4 bav = *(const float4*)&ba[tx * 4];
#pragma unroll
    for (int rp = 0; rp < 4; rp++) {
        float2 c0 = up2(acc[rp][0]), c1 = up2(acc[rp][1]);
        float2 c2 = up2(acc[rp][2]), c3 = up2(acc[rp][3]);
        int r0 = bm0 + ty * 8 + rp * 2;
        if (r0 < N) {
            float4 yv = make_float4(c0.x, c1.x, c2.x, c3.x);
            *(float4*)&g_y[(size_t)r0 * H + tx * 4] = yv;
            float4 zv = make_float4(fmaf(ep1, yv.x, bav.x), fmaf(ep1, yv.y, bav.y),
                                    fmaf(ep1, yv.z, bav.z), fmaf(ep1, yv.w, bav.w));
            *(float4*)&g_z[(size_t)r0 * H + tx * 4] = zv;
        }
        int r1 = r0 + 1;
        if (r1 < N) {
            float4 yv = make_float4(c0.y, c1.y, c2.y, c3.y);
            *(float4*)&g_y[(size_t)r1 * H + tx * 4] = yv;
            float4 zv = make_float4(fmaf(ep1, yv.x, bav.x), fmaf(ep1, yv.y, bav.y),
                                    fmaf(ep1, yv.z, bav.z), fmaf(ep1, yv.w, bav.w));
            *(float4*)&g_z[(size_t)r1 * H + tx * 4] = zv;
        }
    }
}

// ---------------------------------------------------------------------------
// Edge scatter: z[dst] += w * y[src].  16 lanes x float4 per edge.
// Handles int32 or int64 edge_index via g_idx64 flag.
// Block 0 also zeroes the BN stats buffer consumed by the following gemm_b.
// ---------------------------------------------------------------------------
__global__ void scatter_k(const void* __restrict__ ei,
                          const float* __restrict__ ew, int E, int N)
{
    if (blockIdx.x == 0 && threadIdx.x < 2 * H)
        g_stats[threadIdx.x] = 0.f;

    int t = blockIdx.x * blockDim.x + threadIdx.x;
    int e = t >> 4;
    if (e >= E) return;
    int j = (t & 15) * 4;

    long long s, d;
    if (g_idx64) {
        s = ((const long long*)ei)[e];
        d = ((const long long*)ei)[E + e];
    } else {
        s = ((const int*)ei)[e];
        d = ((const int*)ei)[E + e];
    }
    if ((unsigned long long)s >= (unsigned long long)N ||
        (unsigned long long)d >= (unsigned long long)N) return;

    float w = ew[e];
    float4 v = *(const float4*)&g_y[(size_t)s * H + j];
    float* p = &g_z[(size_t)d * H + j];
    asm volatile("red.global.add.v4.f32 [%0], {%1,%2,%3,%4};"
                 :: "l"(p), "f"(w * v.x), "f"(w * v.y), "f"(w * v.z), "f"(w * v.w)
                 : "memory");
}

// ---------------------------------------------------------------------------
// GEMM-B: u = relu(z) @ W + bb ;  plus per-column sum/sumsq into g_stats.
// ---------------------------------------------------------------------------
__global__ __launch_bounds__(256) void gemm_b(
    const float* __restrict__ W, const float* __restrict__ bb, int N)
{
    constexpr int K = 64;
    __shared__ float Ws[K][H];
    __shared__ float As[KC][BM];
    __shared__ float red_s[2 * H];

    const int tid = threadIdx.x;
    const int tx = tid & 15;
    const int ty = tid >> 4;
    const int bm0 = blockIdx.x * BM;

    for (int i = tid * 4; i < K * H; i += 1024)
        *(float4*)((float*)Ws + i) = *(const float4*)&W[i];

    unsigned long long acc[4][4];
#pragma unroll
    for (int i = 0; i < 4; i++)
#pragma unroll
        for (int j = 0; j < 4; j++) acc[i][j] = 0ULL;

    for (int kb = 0; kb < K; kb += KC) {
        __syncthreads();
#pragma unroll
        for (int it = 0; it < 2; it++) {
            int e  = it * 256 + tid;
            int rl = e >> 2;
            int kq = (e & 3) * 4;
            int r  = bm0 + rl;
            float4 v = make_float4(0.f, 0.f, 0.f, 0.f);
            if (r < N) {
                v = *(const float4*)&g_z[(size_t)r * K + kb + kq];
                v.x = fmaxf(v.x, 0.f); v.y = fmaxf(v.y, 0.f);
                v.z = fmaxf(v.z, 0.f); v.w = fmaxf(v.w, 0.f);
            }
            As[kq + 0][rl] = v.x; As[kq + 1][rl] = v.y;
            As[kq + 2][rl] = v.z; As[kq + 3][rl] = v.w;
        }
        __syncthreads();
#pragma unroll
        for (int k = 0; k < KC; k++) {
            float4 a0 = *(float4*)&As[k][ty * 8];
            float4 a1 = *(float4*)&As[k][ty * 8 + 4];
            float4 w  = *(float4*)&Ws[kb + k][tx * 4];
            unsigned long long ap[4] = { pk2(a0.x, a0.y), pk2(a0.z, a0.w),
                                         pk2(a1.x, a1.y), pk2(a1.z, a1.w) };
            unsigned long long wd[4] = { pk2(w.x, w.x), pk2(w.y, w.y),
                                         pk2(w.z, w.z), pk2(w.w, w.w) };
#pragma unroll
            for (int rp = 0; rp < 4; rp++)
#pragma unroll
                for (int c = 0; c < 4; c++) fma2(acc[rp][c], ap[rp], wd[c]);
        }
    }

    const float4 bbv = *(const float4*)&bb[tx * 4];
    float s1[4] = {0.f, 0.f, 0.f, 0.f};
    float s2[4] = {0.f, 0.f, 0.f, 0.f};
#pragma unroll
    for (int rp = 0; rp < 4; rp++) {
        float2 c0 = up2(acc[rp][0]), c1 = up2(acc[rp][1]);
        float2 c2 = up2(acc[rp][2]), c3 = up2(acc[rp][3]);
        int r0 = bm0 + ty * 8 + rp * 2;
        if (r0 < N) {
            float4 o = make_float4(c0.x + bbv.x, c1.x + bbv.y, c2.x + bbv.z, c3.x + bbv.w);
            *(float4*)&g_u[(size_t)r0 * H + tx * 4] = o;
            s1[0] += o.x; s1[1] += o.y; s1[2] += o.z; s1[3] += o.w;
            s2[0] += o.x * o.x; s2[1] += o.y * o.y; s2[2] += o.z * o.z; s2[3] += o.w * o.w;
        }
        int r1 = r0 + 1;
        if (r1 < N) {
            float4 o = make_float4(c0.y + bbv.x, c1.y + bbv.y, c2.y + bbv.z, c3.y + bbv.w);
            *(float4*)&g_u[(size_t)r1 * H + tx * 4] = o;
            s1[0] += o.x; s1[1] += o.y; s1[2] += o.z; s1[3] += o.w;
            s2[0] += o.x * o.x; s2[1] += o.y * o.y; s2[2] += o.z * o.z; s2[3] += o.w * o.w;
        }
    }
    __syncthreads();
    if (tid < 2 * H) red_s[tid] = 0.f;
    __syncthreads();
#pragma unroll
    for (int c = 0; c < 4; c++) {
        atomicAdd(&red_s[tx * 4 + c], s1[c]);
        atomicAdd(&red_s[H + tx * 4 + c], s2[c]);
    }
    __syncthreads();
    if (tid < 2 * H) atomicAdd(&g_stats[tid], red_s[tid]);
}

// ---------------------------------------------------------------------------
// BN affine + relu (+ residual).  out = ext_out ? ext_out : g_h.
// ---------------------------------------------------------------------------
__global__ __launch_bounds__(256) void bn_apply(
    const float* __restrict__ gamma, const float* __restrict__ beta,
    int N, int residual, float* __restrict__ ext_out)
{
    __shared__ float sc[H], sh[H];
    int tid = threadIdx.x;
    if (tid < H) {
        float inv = 1.f / (float)N;
        float m   = g_stats[tid] * inv;
        float var = g_stats[H + tid] * inv - m * m;
        float s   = gamma[tid] * rsqrtf(var + 1e-5f);
        sc[tid] = s;
        sh[tid] = beta[tid] - m * s;
    }
    __syncthreads();
    int i = blockIdx.x * blockDim.x + tid;
    if (i >= N * (H / 4)) return;
    int c = (i & 15) * 4;
    float4 v = ((const float4*)g_u)[i];
    v.x = fmaxf(fmaf(v.x, sc[c + 0], sh[c + 0]), 0.f);
    v.y = fmaxf(fmaf(v.y, sc[c + 1], sh[c + 1]), 0.f);
    v.z = fmaxf(fmaf(v.z, sc[c + 2], sh[c + 2]), 0.f);
    v.w = fmaxf(fmaf(v.w, sc[c + 3], sh[c + 3]), 0.f);
    if (residual) {
        float4 p = ((const float4*)g_h)[i];
        v.x += p.x; v.y += p.y; v.z += p.z; v.w += p.w;
    }
    float4* outp = ext_out ? (float4*)ext_out : (float4*)g_h;
    outp[i] = v;
}

// ---------------------------------------------------------------------------
extern "C" void kernel_launch(void* const* d_in, const int* in_sizes, int n_in,
                              void* d_out, int out_size)
{
    const float* x    = (const float*)d_in[0];
    const void*  ei   = d_in[1];
    const float* ew   = (const float*)d_in[2];
    const float* eps1 = (const float*)d_in[3];
    const float* W1a  = (const float*)d_in[4];
    const float* b1a  = (const float*)d_in[5];
    const float* W1b  = (const float*)d_in[6];
    const float* b1b  = (const float*)d_in[7];
    const float* g1   = (const float*)d_in[8];
    const float* be1  = (const float*)d_in[9];
    const float* epss = (const float*)d_in[10];
    const float* Wsa  = (const float*)d_in[11];
    const float* bsa  = (const float*)d_in[12];
    const float* Wsb  = (const float*)d_in[13];
    const float* bsb  = (const float*)d_in[14];
    const float* gs   = (const float*)d_in[15];
    const float* bes  = (const float*)d_in[16];

    const int N  = in_sizes[0] / 128;
    const int E  = in_sizes[2];
    const int nb = (N + BM - 1) / BM;
    const int eb = (E * 16 + 255) / 256;
    const int ub = (N * (H / 4) + 255) / 256;

    detect_k<<<1, 1>>>((const unsigned*)ei);

    // ---- layer 1 (K = 128) ----
    gemm_a<128><<<nb, 256>>>(x, W1a, b1a, eps1, N);
    scatter_k<<<eb, 256>>>(ei, ew, E, N);
    gemm_b<<<nb, 256>>>(W1b, b1b, N);
    bn_apply<<<ub, 256>>>(g1, be1, N, 0, nullptr);

    // ---- layer 2 ----
    gemm_a<64><<<nb, 256>>>(nullptr, Wsa, bsa, epss, N);
    scatter_k<<<eb, 256>>>(ei, ew, E, N);
    gemm_b<<<nb, 256>>>(Wsb, bsb, N);
    bn_apply<<<ub, 256>>>(gs, bes, N, 1, nullptr);

    // ---- layer 3 ----
    gemm_a<64><<<nb, 256>>>(nullptr, Wsa + 64 * 64, bsa + 64, epss + 1, N);
    scatter_k<<<eb, 256>>>(ei, ew, E, N);
    gemm_b<<<nb, 256>>>(Wsb + 64 * 64, bsb + 64, N);
    bn_apply<<<ub, 256>>>(gs + 64, bes + 64, N, 1, (float*)d_out);
}

// round 6
// speedup vs baseline: 1.0664x; 1.0664x over previous
#include <cuda_runtime.h>
#include <cstdint>
#include <cstddef>

// ---------------------------------------------------------------------------
// BaseGIN: 3-layer GIN on a 100k-node / 1.6M-edge graph.
//
// Per layer (project-then-aggregate; aggregation is linear):
//   y = A_in @ Wa                      (GEMM-A, K=128 for layer 1 else 64)
//   z[n] = (1+eps)*y[n] + ba + sum_{e: dst=n} w_e * y[src_e]   (CSR gather)
//   u = relu(z) @ Wb + bb              (GEMM-B, relu fused on A-load)
//   stats: per-column sum / sumsq of u (fused into GEMM-B epilogue)
//   h' = relu((u-mean)*rsqrt(var+eps)*gamma + beta)  [+ h  for layers 2,3]
//
// CSR (rowptr by dst, permuted src+weight) is built once per launch and
// reused by all 3 layers — removes the 409MB/layer of L2 atomic RMW traffic
// that dominated the Round-3 profile.
// ---------------------------------------------------------------------------

static constexpr int H    = 64;
static constexpr int BM   = 128;   // rows per GEMM block
static constexpr int KC   = 16;    // k-chunk
static constexpr int MAXN = 131072;
static constexpr int MAXE = 1700000;

__device__ __align__(16) float g_y[MAXN * H];
__device__ __align__(16) float g_z[MAXN * H];
__device__ __align__(16) float g_u[MAXN * H];
__device__ __align__(16) float g_h[MAXN * H];
__device__ float g_stats[2 * H];
__device__ int   g_idx64;            // 1 if edge_index is int64, 0 if int32
__device__ int   g_deg[MAXN];
__device__ int   g_rowptr[MAXN + 1];
__device__ int   g_wptr[MAXN];
__device__ int   g_esrc[MAXE];
__device__ float g_ewp[MAXE];

// ---- packed f32x2 helpers (Blackwell FFMA2 is only reachable via PTX) -----
__device__ __forceinline__ unsigned long long pk2(float a, float b) {
    unsigned long long r;
    asm("mov.b64 %0, {%1,%2};" : "=l"(r) : "f"(a), "f"(b));
    return r;
}
__device__ __forceinline__ void fma2(unsigned long long& d,
                                     unsigned long long a, unsigned long long b) {
    asm("fma.rn.f32x2 %0, %1, %2, %0;" : "+l"(d) : "l"(a), "l"(b));
}
__device__ __forceinline__ float2 up2(unsigned long long v) {
    float lo, hi;
    asm("mov.b64 {%0,%1}, %2;" : "=f"(lo), "=f"(hi) : "l"(v));
    return make_float2(lo, hi);
}

// ---------------------------------------------------------------------------
// Detect edge_index dtype (int64 vs int32) — odd 32-bit words of int64
// indices < 2^31 are all zero.
// ---------------------------------------------------------------------------
__global__ void detect_k(const unsigned* __restrict__ ei32) {
    int is64 = 1;
#pragma unroll
    for (int i = 0; i < 64; i++)
        if (ei32[2 * i + 1] != 0u) is64 = 0;
    g_idx64 = is64;
}

__device__ __forceinline__ long long load_idx(const void* ei, int pos) {
    return g_idx64 ? ((const long long*)ei)[pos] : (long long)((const int*)ei)[pos];
}

// ---------------------------------------------------------------------------
// CSR build: zero degrees -> histogram -> scan -> permuted fill
// ---------------------------------------------------------------------------
__global__ void zero_deg_k(int N) {
    int i = blockIdx.x * blockDim.x + threadIdx.x;
    if (i < N) g_deg[i] = 0;
}

__global__ void hist_k(const void* __restrict__ ei, int E, int N) {
    int e = blockIdx.x * blockDim.x + threadIdx.x;
    if (e >= E) return;
    long long d = load_idx(ei, E + e);
    if ((unsigned long long)d < (unsigned long long)N)
        atomicAdd(&g_deg[(int)d], 1);
}

// single-block exclusive scan of g_deg[0..N) into g_rowptr / g_wptr
__global__ __launch_bounds__(1024) void scan_k(int N) {
    __shared__ int part[1024];
    int t  = threadIdx.x;
    int ch = (N + 1023) / 1024;
    int lo = t * ch;
    int hi = min(lo + ch, N);
    int s = 0;
    for (int i = lo; i < hi; i++) s += g_deg[i];
    part[t] = s;
    __syncthreads();
    for (int off = 1; off < 1024; off <<= 1) {
        int v = (t >= off) ? part[t - off] : 0;
        __syncthreads();
        part[t] += v;
        __syncthreads();
    }
    int run = part[t] - s;           // exclusive base for this chunk
    for (int i = lo; i < hi; i++) {
        int d = g_deg[i];
        g_rowptr[i] = run;
        g_wptr[i]   = run;
        run += d;
    }
    if (t == 1023) g_rowptr[N] = part[1023];
}

__global__ void fill_k(const void* __restrict__ ei,
                       const float* __restrict__ ew, int E, int N) {
    int e = blockIdx.x * blockDim.x + threadIdx.x;
    if (e >= E) return;
    long long s = load_idx(ei, e);
    long long d = load_idx(ei, E + e);
    if ((unsigned long long)s >= (unsigned long long)N ||
        (unsigned long long)d >= (unsigned long long)N) return;
    int pos = atomicAdd(&g_wptr[(int)d], 1);
    g_esrc[pos] = (int)s;
    g_ewp[pos]  = ew[e];
}

// ---------------------------------------------------------------------------
// GEMM-A: y = A @ W   (no z output — gather computes z)
// ---------------------------------------------------------------------------
template <int K>
__global__ __launch_bounds__(256) void gemm_a(
    const float* __restrict__ Ain, const float* __restrict__ W, int N)
{
    const float* A = (K == 128) ? Ain : (const float*)g_h;
    __shared__ float Ws[K][H];
    __shared__ float As[KC][BM];

    const int tid = threadIdx.x;
    const int tx = tid & 15;
    const int ty = tid >> 4;
    const int bm0 = blockIdx.x * BM;

    for (int i = tid * 4; i < K * H; i += 1024)
        *(float4*)((float*)Ws + i) = *(const float4*)&W[i];

    unsigned long long acc[4][4];
#pragma unroll
    for (int i = 0; i < 4; i++)
#pragma unroll
        for (int j = 0; j < 4; j++) acc[i][j] = 0ULL;

    for (int kb = 0; kb < K; kb += KC) {
        __syncthreads();
#pragma unroll
        for (int it = 0; it < 2; it++) {
            int e  = it * 256 + tid;
            int rl = e >> 2;
            int kq = (e & 3) * 4;
            int r  = bm0 + rl;
            float4 v = make_float4(0.f, 0.f, 0.f, 0.f);
            if (r < N) v = *(const float4*)&A[(size_t)r * K + kb + kq];
            As[kq + 0][rl] = v.x; As[kq + 1][rl] = v.y;
            As[kq + 2][rl] = v.z; As[kq + 3][rl] = v.w;
        }
        __syncthreads();
#pragma unroll
        for (int k = 0; k < KC; k++) {
            float4 a0 = *(float4*)&As[k][ty * 8];
            float4 a1 = *(float4*)&As[k][ty * 8 + 4];
            float4 w  = *(float4*)&Ws[kb + k][tx * 4];
            unsigned long long ap[4] = { pk2(a0.x, a0.y), pk2(a0.z, a0.w),
                                         pk2(a1.x, a1.y), pk2(a1.z, a1.w) };
            unsigned long long wd[4] = { pk2(w.x, w.x), pk2(w.y, w.y),
                                         pk2(w.z, w.z), pk2(w.w, w.w) };
#pragma unroll
            for (int rp = 0; rp < 4; rp++)
#pragma unroll
                for (int c = 0; c < 4; c++) fma2(acc[rp][c], ap[rp], wd[c]);
        }
    }

#pragma unroll
    for (int rp = 0; rp < 4; rp++) {
        float2 c0 = up2(acc[rp][0]), c1 = up2(acc[rp][1]);
        float2 c2 = up2(acc[rp][2]), c3 = up2(acc[rp][3]);
        int r0 = bm0 + ty * 8 + rp * 2;
        if (r0 < N)
            *(float4*)&g_y[(size_t)r0 * H + tx * 4] =
                make_float4(c0.x, c1.x, c2.x, c3.x);
        int r1 = r0 + 1;
        if (r1 < N)
            *(float4*)&g_y[(size_t)r1 * H + tx * 4] =
                make_float4(c0.y, c1.y, c2.y, c3.y);
    }
}

// ---------------------------------------------------------------------------
// CSR gather: z[n] = (1+eps)*y[n] + ba + sum_e w_e * y[src_e]
// 16 lanes per node (float4 per lane); inner loop unrolled x2 for MLP.
// Block 0 zeroes BN stats for the following gemm_b.
// ---------------------------------------------------------------------------
__global__ __launch_bounds__(256) void gather_k(
    const float* __restrict__ ba, const float* __restrict__ eps_p, int N)
{
    if (blockIdx.x == 0 && threadIdx.x < 2 * H)
        g_stats[threadIdx.x] = 0.f;

    int t = blockIdx.x * blockDim.x + threadIdx.x;
    int n = t >> 4;
    if (n >= N) return;
    int j = (t & 15) * 4;

    int beg = g_rowptr[n];
    int end = g_rowptr[n + 1];
    float4 acc0 = make_float4(0.f, 0.f, 0.f, 0.f);
    float4 acc1 = make_float4(0.f, 0.f, 0.f, 0.f);
    int e = beg;
    for (; e + 1 < end; e += 2) {
        int   s0 = g_esrc[e],     s1 = g_esrc[e + 1];
        float w0 = g_ewp[e];
        float w1 = g_ewp[e + 1];
        float4 v0 = *(const float4*)&g_y[(size_t)s0 * H + j];
        float4 v1 = *(const float4*)&g_y[(size_t)s1 * H + j];
        acc0.x += w0 * v0.x; acc0.y += w0 * v0.y;
        acc0.z += w0 * v0.z; acc0.w += w0 * v0.w;
        acc1.x += w1 * v1.x; acc1.y += w1 * v1.y;
        acc1.z += w1 * v1.z; acc1.w += w1 * v1.w;
    }
    if (e < end) {
        int   s = g_esrc[e];
        float w = g_ewp[e];
        float4 v = *(const float4*)&g_y[(size_t)s * H + j];
        acc0.x += w * v.x; acc0.y += w * v.y;
        acc0.z += w * v.z; acc0.w += w * v.w;
    }
    acc0.x += acc1.x; acc0.y += acc1.y; acc0.z += acc1.z; acc0.w += acc1.w;

    const float ep1 = 1.0f + *eps_p;
    float4 yv  = *(const float4*)&g_y[(size_t)n * H + j];
    float4 bav = *(const float4*)&ba[j];
    float4 zv  = make_float4(fmaf(ep1, yv.x, bav.x + acc0.x),
                             fmaf(ep1, yv.y, bav.y + acc0.y),
                             fmaf(ep1, yv.z, bav.z + acc0.z),
                             fmaf(ep1, yv.w, bav.w + acc0.w));
    *(float4*)&g_z[(size_t)n * H + j] = zv;
}

// ---------------------------------------------------------------------------
// GEMM-B: u = relu(z) @ W + bb ;  plus per-column sum/sumsq into g_stats.
// ---------------------------------------------------------------------------
__global__ __launch_bounds__(256) void gemm_b(
    const float* __restrict__ W, const float* __restrict__ bb, int N)
{
    constexpr int K = 64;
    __shared__ float Ws[K][H];
    __shared__ float As[KC][BM];
    __shared__ float red_s[2 * H];

    const int tid = threadIdx.x;
    const int tx = tid & 15;
    const int ty = tid >> 4;
    const int bm0 = blockIdx.x * BM;

    for (int i = tid * 4; i < K * H; i += 1024)
        *(float4*)((float*)Ws + i) = *(const float4*)&W[i];

    unsigned long long acc[4][4];
#pragma unroll
    for (int i = 0; i < 4; i++)
#pragma unroll
        for (int j = 0; j < 4; j++) acc[i][j] = 0ULL;

    for (int kb = 0; kb < K; kb += KC) {
        __syncthreads();
#pragma unroll
        for (int it = 0; it < 2; it++) {
            int e  = it * 256 + tid;
            int rl = e >> 2;
            int kq = (e & 3) * 4;
            int r  = bm0 + rl;
            float4 v = make_float4(0.f, 0.f, 0.f, 0.f);
            if (r < N) {
                v = *(const float4*)&g_z[(size_t)r * K + kb + kq];
                v.x = fmaxf(v.x, 0.f); v.y = fmaxf(v.y, 0.f);
                v.z = fmaxf(v.z, 0.f); v.w = fmaxf(v.w, 0.f);
            }
            As[kq + 0][rl] = v.x; As[kq + 1][rl] = v.y;
            As[kq + 2][rl] = v.z; As[kq + 3][rl] = v.w;
        }
        __syncthreads();
#pragma unroll
        for (int k = 0; k < KC; k++) {
            float4 a0 = *(float4*)&As[k][ty * 8];
            float4 a1 = *(float4*)&As[k][ty * 8 + 4];
            float4 w  = *(float4*)&Ws[kb + k][tx * 4];
            unsigned long long ap[4] = { pk2(a0.x, a0.y), pk2(a0.z, a0.w),
                                         pk2(a1.x, a1.y), pk2(a1.z, a1.w) };
            unsigned long long wd[4] = { pk2(w.x, w.x), pk2(w.y, w.y),
                                         pk2(w.z, w.z), pk2(w.w, w.w) };
#pragma unroll
            for (int rp = 0; rp < 4; rp++)
#pragma unroll
                for (int c = 0; c < 4; c++) fma2(acc[rp][c], ap[rp], wd[c]);
        }
    }

    const float4 bbv = *(const float4*)&bb[tx * 4];
    float s1[4] = {0.f, 0.f, 0.f, 0.f};
    float s2[4] = {0.f, 0.f, 0.f, 0.f};
#pragma unroll
    for (int rp = 0; rp < 4; rp++) {
        float2 c0 = up2(acc[rp][0]), c1 = up2(acc[rp][1]);
        float2 c2 = up2(acc[rp][2]), c3 = up2(acc[rp][3]);
        int r0 = bm0 + ty * 8 + rp * 2;
        if (r0 < N) {
            float4 o = make_float4(c0.x + bbv.x, c1.x + bbv.y, c2.x + bbv.z, c3.x + bbv.w);
            *(float4*)&g_u[(size_t)r0 * H + tx * 4] = o;
            s1[0] += o.x; s1[1] += o.y; s1[2] += o.z; s1[3] += o.w;
            s2[0] += o.x * o.x; s2[1] += o.y * o.y; s2[2] += o.z * o.z; s2[3] += o.w * o.w;
        }
        int r1 = r0 + 1;
        if (r1 < N) {
            float4 o = make_float4(c0.y + bbv.x, c1.y + bbv.y, c2.y + bbv.z, c3.y + bbv.w);
            *(float4*)&g_u[(size_t)r1 * H + tx * 4] = o;
            s1[0] += o.x; s1[1] += o.y; s1[2] += o.z; s1[3] += o.w;
            s2[0] += o.x * o.x; s2[1] += o.y * o.y; s2[2] += o.z * o.z; s2[3] += o.w * o.w;
        }
    }
    __syncthreads();
    if (tid < 2 * H) red_s[tid] = 0.f;
    __syncthreads();
#pragma unroll
    for (int c = 0; c < 4; c++) {
        atomicAdd(&red_s[tx * 4 + c], s1[c]);
        atomicAdd(&red_s[H + tx * 4 + c], s2[c]);
    }
    __syncthreads();
    if (tid < 2 * H) atomicAdd(&g_stats[tid], red_s[tid]);
}

// ---------------------------------------------------------------------------
// BN affine + relu (+ residual).  out = ext_out ? ext_out : g_h.
// ---------------------------------------------------------------------------
__global__ __launch_bounds__(256) void bn_apply(
    const float* __restrict__ gamma, const float* __restrict__ beta,
    int N, int residual, float* __restrict__ ext_out)
{
    __shared__ float sc[H], sh[H];
    int tid = threadIdx.x;
    if (tid < H) {
        float inv = 1.f / (float)N;
        float m   = g_stats[tid] * inv;
        float var = g_stats[H + tid] * inv - m * m;
        float s   = gamma[tid] * rsqrtf(var + 1e-5f);
        sc[tid] = s;
        sh[tid] = beta[tid] - m * s;
    }
    __syncthreads();
    int i = blockIdx.x * blockDim.x + tid;
    if (i >= N * (H / 4)) return;
    int c = (i & 15) * 4;
    float4 v = ((const float4*)g_u)[i];
    v.x = fmaxf(fmaf(v.x, sc[c + 0], sh[c + 0]), 0.f);
    v.y = fmaxf(fmaf(v.y, sc[c + 1], sh[c + 1]), 0.f);
    v.z = fmaxf(fmaf(v.z, sc[c + 2], sh[c + 2]), 0.f);
    v.w = fmaxf(fmaf(v.w, sc[c + 3], sh[c + 3]), 0.f);
    if (residual) {
        float4 p = ((const float4*)g_h)[i];
        v.x += p.x; v.y += p.y; v.z += p.z; v.w += p.w;
    }
    float4* outp = ext_out ? (float4*)ext_out : (float4*)g_h;
    outp[i] = v;
}

// ---------------------------------------------------------------------------
extern "C" void kernel_launch(void* const* d_in, const int* in_sizes, int n_in,
                              void* d_out, int out_size)
{
    const float* x    = (const float*)d_in[0];
    const void*  ei   = d_in[1];
    const float* ew   = (const float*)d_in[2];
    const float* eps1 = (const float*)d_in[3];
    const float* W1a  = (const float*)d_in[4];
    const float* b1a  = (const float*)d_in[5];
    const float* W1b  = (const float*)d_in[6];
    const float* b1b  = (const float*)d_in[7];
    const float* g1   = (const float*)d_in[8];
    const float* be1  = (const float*)d_in[9];
    const float* epss = (const float*)d_in[10];
    const float* Wsa  = (const float*)d_in[11];
    const float* bsa  = (const float*)d_in[12];
    const float* Wsb  = (const float*)d_in[13];
    const float* bsb  = (const float*)d_in[14];
    const float* gs   = (const float*)d_in[15];
    const float* bes  = (const float*)d_in[16];

    const int N  = in_sizes[0] / 128;
    const int E  = in_sizes[2];
    const int nb = (N + BM - 1) / BM;
    const int eb = (E + 255) / 256;
    const int gb = (N * 16 + 255) / 256;
    const int ub = (N * (H / 4) + 255) / 256;

    // ---- CSR build (once; reused by all 3 layers) ----
    detect_k<<<1, 1>>>((const unsigned*)ei);
    zero_deg_k<<<(N + 255) / 256, 256>>>(N);
    hist_k<<<eb, 256>>>(ei, E, N);
    scan_k<<<1, 1024>>>(N);
    fill_k<<<eb, 256>>>(ei, ew, E, N);

    // ---- layer 1 (K = 128) ----
    gemm_a<128><<<nb, 256>>>(x, W1a, N);
    gather_k<<<gb, 256>>>(b1a, eps1, N);
    gemm_b<<<nb, 256>>>(W1b, b1b, N);
    bn_apply<<<ub, 256>>>(g1, be1, N, 0, nullptr);

    // ---- layer 2 ----
    gemm_a<64><<<nb, 256>>>(nullptr, Wsa, N);
    gather_k<<<gb, 256>>>(bsa, epss, N);
    gemm_b<<<nb, 256>>>(Wsb, bsb, N);
    bn_apply<<<ub, 256>>>(gs, bes, N, 1, nullptr);

    // ---- layer 3 ----
    gemm_a<64><<<nb, 256>>>(nullptr, Wsa + 64 * 64, N);
    gather_k<<<gb, 256>>>(bsa + 64, epss + 1, N);
    gemm_b<<<nb, 256>>>(Wsb + 64 * 64, bsb + 64, N);
    bn_apply<<<ub, 256>>>(gs + 64, bes + 64, N, 1, (float*)d_out);
}

// round 7
// speedup vs baseline: 1.4961x; 1.4030x over previous
#include <cuda_runtime.h>
#include <cstdint>
#include <cstddef>

// ---------------------------------------------------------------------------
// BaseGIN: 3-layer GIN on a 100k-node / 1.6M-edge graph.
//
// Per layer (project-then-aggregate; aggregation is linear):
//   y = A_in @ Wa                      (GEMM-A, K=128 for layer 1 else 64)
//   z[n] = (1+eps)*y[n] + ba + sum_{e: dst=n} w_e * y[src_e]   (CSR gather)
//   u = relu(z) @ Wb + bb              (GEMM-B, relu fused on A-load)
//   stats: per-column sum / sumsq of u (fused into GEMM-B epilogue)
//   h' = relu((u-mean)*rsqrt(var+eps)*gamma + beta)  [+ h  for layers 2,3]
//
// CSR built once per launch. Round-6 profile showed the single-block scan
// at 166us (issue=2.3%); replaced with a 3-phase multi-block scan.
// ---------------------------------------------------------------------------

static constexpr int H    = 64;
static constexpr int BM   = 128;   // rows per GEMM block
static constexpr int KC   = 16;    // k-chunk
static constexpr int MAXN = 131072;
static constexpr int MAXE = 1700000;
static constexpr int SCAN_EPB = 2048;            // elements per scan block

__device__ __align__(16) float g_y[MAXN * H];
__device__ __align__(16) float g_z[MAXN * H];
__device__ __align__(16) float g_u[MAXN * H];
__device__ __align__(16) float g_h[MAXN * H];
__device__ float g_stats[2 * H];
__device__ int   g_idx64;            // 1 if edge_index is int64, 0 if int32
__device__ int   g_deg[MAXN];
__device__ int   g_rowptr[MAXN + 1];
__device__ int   g_wptr[MAXN];
__device__ int   g_esrc[MAXE];
__device__ float g_ewp[MAXE];
__device__ int   g_bsum[128];        // per-block degree sums (<=64 used)

// ---- packed f32x2 helpers (Blackwell FFMA2 is only reachable via PTX) -----
__device__ __forceinline__ unsigned long long pk2(float a, float b) {
    unsigned long long r;
    asm("mov.b64 %0, {%1,%2};" : "=l"(r) : "f"(a), "f"(b));
    return r;
}
__device__ __forceinline__ void fma2(unsigned long long& d,
                                     unsigned long long a, unsigned long long b) {
    asm("fma.rn.f32x2 %0, %1, %2, %0;" : "+l"(d) : "l"(a), "l"(b));
}
__device__ __forceinline__ float2 up2(unsigned long long v) {
    float lo, hi;
    asm("mov.b64 {%0,%1}, %2;" : "=f"(lo), "=f"(hi) : "l"(v));
    return make_float2(lo, hi);
}

// ---------------------------------------------------------------------------
// Detect edge_index dtype (int64 vs int32) — odd 32-bit words of int64
// indices < 2^31 are all zero.
// ---------------------------------------------------------------------------
__global__ void detect_k(const unsigned* __restrict__ ei32) {
    int is64 = 1;
#pragma unroll
    for (int i = 0; i < 64; i++)
        if (ei32[2 * i + 1] != 0u) is64 = 0;
    g_idx64 = is64;
}

__device__ __forceinline__ long long load_idx(const void* ei, int pos) {
    return g_idx64 ? ((const long long*)ei)[pos] : (long long)((const int*)ei)[pos];
}

// ---------------------------------------------------------------------------
// CSR build: zero -> histogram -> 3-phase scan -> permuted fill
// ---------------------------------------------------------------------------
__global__ void zero_deg_k(int N) {
    int i = blockIdx.x * blockDim.x + threadIdx.x;
    if (i < N) g_deg[i] = 0;
}

__global__ void hist_k(const void* __restrict__ ei, int E, int N) {
    int e = blockIdx.x * blockDim.x + threadIdx.x;
    if (e >= E) return;
    long long d = load_idx(ei, E + e);
    if ((unsigned long long)d < (unsigned long long)N)
        atomicAdd(&g_deg[(int)d], 1);
}

// Phase 1: per-block degree sums (each block owns SCAN_EPB contiguous elems)
__global__ __launch_bounds__(256) void scan_sum_k(int N) {
    int b = blockIdx.x, t = threadIdx.x;
    int base = b * SCAN_EPB + t * 8;
    int s = 0;
#pragma unroll
    for (int i = 0; i < 8; i++) {
        int idx = base + i;
        if (idx < N) s += g_deg[idx];
    }
    __shared__ int red[256];
    red[t] = s;
    __syncthreads();
    for (int off = 128; off > 0; off >>= 1) {
        if (t < off) red[t] += red[t + off];
        __syncthreads();
    }
    if (t == 0) g_bsum[b] = red[0];
}

// Phase 2: exclusive scan of block sums (single small block); rowptr[N]=total
__global__ __launch_bounds__(128) void scan_top_k(int nb, int N) {
    __shared__ int sh[128];
    int t = threadIdx.x;
    int v = (t < nb) ? g_bsum[t] : 0;
    sh[t] = v;
    __syncthreads();
    for (int off = 1; off < 128; off <<= 1) {
        int u = (t >= off) ? sh[t - off] : 0;
        __syncthreads();
        sh[t] += u;
        __syncthreads();
    }
    if (t < nb) g_bsum[t] = sh[t] - v;   // exclusive base per block
    if (t == 127) g_rowptr[N] = sh[127]; // grand total
}

// Phase 3: per-block exclusive scan + write rowptr/wptr
__global__ __launch_bounds__(256) void scan_apply_k(int N) {
    int b = blockIdx.x, t = threadIdx.x;
    int base = b * SCAN_EPB + t * 8;
    int d[8];
    int s = 0;
#pragma unroll
    for (int i = 0; i < 8; i++) {
        int idx = base + i;
        d[i] = (idx < N) ? g_deg[idx] : 0;
        s += d[i];
    }
    __shared__ int sh[256];
    sh[t] = s;
    __syncthreads();
    for (int off = 1; off < 256; off <<= 1) {
        int u = (t >= off) ? sh[t - off] : 0;
        __syncthreads();
        sh[t] += u;
        __syncthreads();
    }
    int run = g_bsum[b] + sh[t] - s;     // exclusive prefix for this thread
#pragma unroll
    for (int i = 0; i < 8; i++) {
        int idx = base + i;
        if (idx < N) { g_rowptr[idx] = run; g_wptr[idx] = run; }
        run += d[i];
    }
}

__global__ void fill_k(const void* __restrict__ ei,
                       const float* __restrict__ ew, int E, int N) {
    int e = blockIdx.x * blockDim.x + threadIdx.x;
    if (e >= E) return;
    long long s = load_idx(ei, e);
    long long d = load_idx(ei, E + e);
    if ((unsigned long long)s >= (unsigned long long)N ||
        (unsigned long long)d >= (unsigned long long)N) return;
    int pos = atomicAdd(&g_wptr[(int)d], 1);
    g_esrc[pos] = (int)s;
    g_ewp[pos]  = ew[e];
}

// ---------------------------------------------------------------------------
// GEMM-A: y = A @ W   (no z output — gather computes z)
// ---------------------------------------------------------------------------
template <int K>
__global__ __launch_bounds__(256) void gemm_a(
    const float* __restrict__ Ain, const float* __restrict__ W, int N)
{
    const float* A = (K == 128) ? Ain : (const float*)g_h;
    __shared__ float Ws[K][H];
    __shared__ float As[KC][BM];

    const int tid = threadIdx.x;
    const int tx = tid & 15;
    const int ty = tid >> 4;
    const int bm0 = blockIdx.x * BM;

    for (int i = tid * 4; i < K * H; i += 1024)
        *(float4*)((float*)Ws + i) = *(const float4*)&W[i];

    unsigned long long acc[4][4];
#pragma unroll
    for (int i = 0; i < 4; i++)
#pragma unroll
        for (int j = 0; j < 4; j++) acc[i][j] = 0ULL;

    for (int kb = 0; kb < K; kb += KC) {
        __syncthreads();
#pragma unroll
        for (int it = 0; it < 2; it++) {
            int e  = it * 256 + tid;
            int rl = e >> 2;
            int kq = (e & 3) * 4;
            int r  = bm0 + rl;
            float4 v = make_float4(0.f, 0.f, 0.f, 0.f);
            if (r < N) v = *(const float4*)&A[(size_t)r * K + kb + kq];
            As[kq + 0][rl] = v.x; As[kq + 1][rl] = v.y;
            As[kq + 2][rl] = v.z; As[kq + 3][rl] = v.w;
        }
        __syncthreads();
#pragma unroll
        for (int k = 0; k < KC; k++) {
            float4 a0 = *(float4*)&As[k][ty * 8];
            float4 a1 = *(float4*)&As[k][ty * 8 + 4];
            float4 w  = *(float4*)&Ws[kb + k][tx * 4];
            unsigned long long ap[4] = { pk2(a0.x, a0.y), pk2(a0.z, a0.w),
                                         pk2(a1.x, a1.y), pk2(a1.z, a1.w) };
            unsigned long long wd[4] = { pk2(w.x, w.x), pk2(w.y, w.y),
                                         pk2(w.z, w.z), pk2(w.w, w.w) };
#pragma unroll
            for (int rp = 0; rp < 4; rp++)
#pragma unroll
                for (int c = 0; c < 4; c++) fma2(acc[rp][c], ap[rp], wd[c]);
        }
    }

#pragma unroll
    for (int rp = 0; rp < 4; rp++) {
        float2 c0 = up2(acc[rp][0]), c1 = up2(acc[rp][1]);
        float2 c2 = up2(acc[rp][2]), c3 = up2(acc[rp][3]);
        int r0 = bm0 + ty * 8 + rp * 2;
        if (r0 < N)
            *(float4*)&g_y[(size_t)r0 * H + tx * 4] =
                make_float4(c0.x, c1.x, c2.x, c3.x);
        int r1 = r0 + 1;
        if (r1 < N)
            *(float4*)&g_y[(size_t)r1 * H + tx * 4] =
                make_float4(c0.y, c1.y, c2.y, c3.y);
    }
}

// ---------------------------------------------------------------------------
// CSR gather: z[n] = (1+eps)*y[n] + ba + sum_e w_e * y[src_e]
// 16 lanes per node (float4 per lane); inner loop unrolled x2 for MLP.
// Block 0 zeroes BN stats for the following gemm_b.
// ---------------------------------------------------------------------------
__global__ __launch_bounds__(256) void gather_k(
    const float* __restrict__ ba, const float* __restrict__ eps_p, int N)
{
    if (blockIdx.x == 0 && threadIdx.x < 2 * H)
        g_stats[threadIdx.x] = 0.f;

    int t = blockIdx.x * blockDim.x + threadIdx.x;
    int n = t >> 4;
    if (n >= N) return;
    int j = (t & 15) * 4;

    int beg = g_rowptr[n];
    int end = g_rowptr[n + 1];
    float4 acc0 = make_float4(0.f, 0.f, 0.f, 0.f);
    float4 acc1 = make_float4(0.f, 0.f, 0.f, 0.f);
    int e = beg;
    for (; e + 1 < end; e += 2) {
        int   s0 = g_esrc[e],     s1 = g_esrc[e + 1];
        float w0 = g_ewp[e];
        float w1 = g_ewp[e + 1];
        float4 v0 = *(const float4*)&g_y[(size_t)s0 * H + j];
        float4 v1 = *(const float4*)&g_y[(size_t)s1 * H + j];
        acc0.x += w0 * v0.x; acc0.y += w0 * v0.y;
        acc0.z += w0 * v0.z; acc0.w += w0 * v0.w;
        acc1.x += w1 * v1.x; acc1.y += w1 * v1.y;
        acc1.z += w1 * v1.z; acc1.w += w1 * v1.w;
    }
    if (e < end) {
        int   s = g_esrc[e];
        float w = g_ewp[e];
        float4 v = *(const float4*)&g_y[(size_t)s * H + j];
        acc0.x += w * v.x; acc0.y += w * v.y;
        acc0.z += w * v.z; acc0.w += w * v.w;
    }
    acc0.x += acc1.x; acc0.y += acc1.y; acc0.z += acc1.z; acc0.w += acc1.w;

    const float ep1 = 1.0f + *eps_p;
    float4 yv  = *(const float4*)&g_y[(size_t)n * H + j];
    float4 bav = *(const float4*)&ba[j];
    float4 zv  = make_float4(fmaf(ep1, yv.x, bav.x + acc0.x),
                             fmaf(ep1, yv.y, bav.y + acc0.y),
                             fmaf(ep1, yv.z, bav.z + acc0.z),
                             fmaf(ep1, yv.w, bav.w + acc0.w));
    *(float4*)&g_z[(size_t)n * H + j] = zv;
}

// ---------------------------------------------------------------------------
// GEMM-B: u = relu(z) @ W + bb ;  plus per-column sum/sumsq into g_stats.
// ---------------------------------------------------------------------------
__global__ __launch_bounds__(256) void gemm_b(
    const float* __restrict__ W, const float* __restrict__ bb, int N)
{
    constexpr int K = 64;
    __shared__ float Ws[K][H];
    __shared__ float As[KC][BM];
    __shared__ float red_s[2 * H];

    const int tid = threadIdx.x;
    const int tx = tid & 15;
    const int ty = tid >> 4;
    const int bm0 = blockIdx.x * BM;

    for (int i = tid * 4; i < K * H; i += 1024)
        *(float4*)((float*)Ws + i) = *(const float4*)&W[i];

    unsigned long long acc[4][4];
#pragma unroll
    for (int i = 0; i < 4; i++)
#pragma unroll
        for (int j = 0; j < 4; j++) acc[i][j] = 0ULL;

    for (int kb = 0; kb < K; kb += KC) {
        __syncthreads();
#pragma unroll
        for (int it = 0; it < 2; it++) {
            int e  = it * 256 + tid;
            int rl = e >> 2;
            int kq = (e & 3) * 4;
            int r  = bm0 + rl;
            float4 v = make_float4(0.f, 0.f, 0.f, 0.f);
            if (r < N) {
                v = *(const float4*)&g_z[(size_t)r * K + kb + kq];
                v.x = fmaxf(v.x, 0.f); v.y = fmaxf(v.y, 0.f);
                v.z = fmaxf(v.z, 0.f); v.w = fmaxf(v.w, 0.f);
            }
            As[kq + 0][rl] = v.x; As[kq + 1][rl] = v.y;
            As[kq + 2][rl] = v.z; As[kq + 3][rl] = v.w;
        }
        __syncthreads();
#pragma unroll
        for (int k = 0; k < KC; k++) {
            float4 a0 = *(float4*)&As[k][ty * 8];
            float4 a1 = *(float4*)&As[k][ty * 8 + 4];
            float4 w  = *(float4*)&Ws[kb + k][tx * 4];
            unsigned long long ap[4] = { pk2(a0.x, a0.y), pk2(a0.z, a0.w),
                                         pk2(a1.x, a1.y), pk2(a1.z, a1.w) };
            unsigned long long wd[4] = { pk2(w.x, w.x), pk2(w.y, w.y),
                                         pk2(w.z, w.z), pk2(w.w, w.w) };
#pragma unroll
            for (int rp = 0; rp < 4; rp++)
#pragma unroll
                for (int c = 0; c < 4; c++) fma2(acc[rp][c], ap[rp], wd[c]);
        }
    }

    const float4 bbv = *(const float4*)&bb[tx * 4];
    float s1[4] = {0.f, 0.f, 0.f, 0.f};
    float s2[4] = {0.f, 0.f, 0.f, 0.f};
#pragma unroll
    for (int rp = 0; rp < 4; rp++) {
        float2 c0 = up2(acc[rp][0]), c1 = up2(acc[rp][1]);
        float2 c2 = up2(acc[rp][2]), c3 = up2(acc[rp][3]);
        int r0 = bm0 + ty * 8 + rp * 2;
        if (r0 < N) {
            float4 o = make_float4(c0.x + bbv.x, c1.x + bbv.y, c2.x + bbv.z, c3.x + bbv.w);
            *(float4*)&g_u[(size_t)r0 * H + tx * 4] = o;
            s1[0] += o.x; s1[1] += o.y; s1[2] += o.z; s1[3] += o.w;
            s2[0] += o.x * o.x; s2[1] += o.y * o.y; s2[2] += o.z * o.z; s2[3] += o.w * o.w;
        }
        int r1 = r0 + 1;
        if (r1 < N) {
            float4 o = make_float4(c0.y + bbv.x, c1.y + bbv.y, c2.y + bbv.z, c3.y + bbv.w);
            *(float4*)&g_u[(size_t)r1 * H + tx * 4] = o;
            s1[0] += o.x; s1[1] += o.y; s1[2] += o.z; s1[3] += o.w;
            s2[0] += o.x * o.x; s2[1] += o.y * o.y; s2[2] += o.z * o.z; s2[3] += o.w * o.w;
        }
    }
    __syncthreads();
    if (tid < 2 * H) red_s[tid] = 0.f;
    __syncthreads();
#pragma unroll
    for (int c = 0; c < 4; c++) {
        atomicAdd(&red_s[tx * 4 + c], s1[c]);
        atomicAdd(&red_s[H + tx * 4 + c], s2[c]);
    }
    __syncthreads();
    if (tid < 2 * H) atomicAdd(&g_stats[tid], red_s[tid]);
}

// ---------------------------------------------------------------------------
// BN affine + relu (+ residual).  out = ext_out ? ext_out : g_h.
// ---------------------------------------------------------------------------
__global__ __launch_bounds__(256) void bn_apply(
    const float* __restrict__ gamma, const float* __restrict__ beta,
    int N, int residual, float* __restrict__ ext_out)
{
    __shared__ float sc[H], sh[H];
    int tid = threadIdx.x;
    if (tid < H) {
        float inv = 1.f / (float)N;
        float m   = g_stats[tid] * inv;
        float var = g_stats[H + tid] * inv - m * m;
        float s   = gamma[tid] * rsqrtf(var + 1e-5f);
        sc[tid] = s;
        sh[tid] = beta[tid] - m * s;
    }
    __syncthreads();
    int i = blockIdx.x * blockDim.x + tid;
    if (i >= N * (H / 4)) return;
    int c = (i & 15) * 4;
    float4 v = ((const float4*)g_u)[i];
    v.x = fmaxf(fmaf(v.x, sc[c + 0], sh[c + 0]), 0.f);
    v.y = fmaxf(fmaf(v.y, sc[c + 1], sh[c + 1]), 0.f);
    v.z = fmaxf(fmaf(v.z, sc[c + 2], sh[c + 2]), 0.f);
    v.w = fmaxf(fmaf(v.w, sc[c + 3], sh[c + 3]), 0.f);
    if (residual) {
        float4 p = ((const float4*)g_h)[i];
        v.x += p.x; v.y += p.y; v.z += p.z; v.w += p.w;
    }
    float4* outp = ext_out ? (float4*)ext_out : (float4*)g_h;
    outp[i] = v;
}

// ---------------------------------------------------------------------------
extern "C" void kernel_launch(void* const* d_in, const int* in_sizes, int n_in,
                              void* d_out, int out_size)
{
    const float* x    = (const float*)d_in[0];
    const void*  ei   = d_in[1];
    const float* ew   = (const float*)d_in[2];
    const float* eps1 = (const float*)d_in[3];
    const float* W1a  = (const float*)d_in[4];
    const float* b1a  = (const float*)d_in[5];
    const float* W1b  = (const float*)d_in[6];
    const float* b1b  = (const float*)d_in[7];
    const float* g1   = (const float*)d_in[8];
    const float* be1  = (const float*)d_in[9];
    const float* epss = (const float*)d_in[10];
    const float* Wsa  = (const float*)d_in[11];
    const float* bsa  = (const float*)d_in[12];
    const float* Wsb  = (const float*)d_in[13];
    const float* bsb  = (const float*)d_in[14];
    const float* gs   = (const float*)d_in[15];
    const float* bes  = (const float*)d_in[16];

    const int N  = in_sizes[0] / 128;
    const int E  = in_sizes[2];
    const int nb = (N + BM - 1) / BM;
    const int eb = (E + 255) / 256;
    const int gb = (N * 16 + 255) / 256;
    const int ub = (N * (H / 4) + 255) / 256;
    const int sb = (N + SCAN_EPB - 1) / SCAN_EPB;

    // ---- CSR build (once; reused by all 3 layers) ----
    detect_k<<<1, 1>>>((const unsigned*)ei);
    zero_deg_k<<<(N + 255) / 256, 256>>>(N);
    hist_k<<<eb, 256>>>(ei, E, N);
    scan_sum_k<<<sb, 256>>>(N);
    scan_top_k<<<1, 128>>>(sb, N);
    scan_apply_k<<<sb, 256>>>(N);
    fill_k<<<eb, 256>>>(ei, ew, E, N);

    // ---- layer 1 (K = 128) ----
    gemm_a<128><<<nb, 256>>>(x, W1a, N);
    gather_k<<<gb, 256>>>(b1a, eps1, N);
    gemm_b<<<nb, 256>>>(W1b, b1b, N);
    bn_apply<<<ub, 256>>>(g1, be1, N, 0, nullptr);

    // ---- layer 2 ----
    gemm_a<64><<<nb, 256>>>(nullptr, Wsa, N);
    gather_k<<<gb, 256>>>(bsa, epss, N);
    gemm_b<<<nb, 256>>>(Wsb, bsb, N);
    bn_apply<<<ub, 256>>>(gs, bes, N, 1, nullptr);

    // ---- layer 3 ----
    gemm_a<64><<<nb, 256>>>(nullptr, Wsa + 64 * 64, N);
    gather_k<<<gb, 256>>>(bsa + 64, epss + 1, N);
    gemm_b<<<nb, 256>>>(Wsb + 64 * 64, bsb + 64, N);
    bn_apply<<<ub, 256>>>(gs + 64, bes + 64, N, 1, (float*)d_out);
}